// round 2
// baseline (speedup 1.0000x reference)
#include <cuda_runtime.h>

// Problem constants (fixed by the dataset reference)
#define SIZE    4096
#define LOG_N   12
#define NPAIRS  (SIZE / 2)          // 2048
#define N4      (SIZE / 4)          // 1024 float4 per row

// Scratch: composite 2x2 matrices, one float4 (m00,m01,m10,m11) per pair.
__device__ float4 g_comp[NPAIRS];

// Kernel 1: compose the 12 per-pair 2x2 matrices into one.
// Row-vector convention: out = v @ W0 @ W1 @ ... @ W11  ==>  M = W0*W1*...*W11.
// Double precision so reassociation error vs the layer-by-layer fp32
// reference is negligible (final fp32 rounding only).
__global__ void butterfly_compose(const float* __restrict__ W) {
    int n = blockIdx.x * blockDim.x + threadIdx.x;
    if (n >= NPAIRS) return;
    double m00 = 1.0, m01 = 0.0, m10 = 0.0, m11 = 1.0;
#pragma unroll
    for (int l = 0; l < LOG_N; ++l) {
        const float4 w = __ldg((const float4*)(W + ((size_t)l * NPAIRS + n) * 4));
        // w = (w00, w01, w10, w11); new M = M @ Wl
        double a00 = m00 * (double)w.x + m01 * (double)w.z;
        double a01 = m00 * (double)w.y + m01 * (double)w.w;
        double a10 = m10 * (double)w.x + m11 * (double)w.z;
        double a11 = m10 * (double)w.y + m11 * (double)w.w;
        m00 = a00; m01 = a01; m10 = a10; m11 = a11;
    }
    g_comp[n] = make_float4((float)m00, (float)m01, (float)m10, (float)m11);
}

// Kernel 2: single streaming pass. Each thread owns one float4 column slot
// (= 2 adjacent pairs), keeps the 2 composite matrices in registers, and
// strides over a row range. Fully coalesced 16B loads/stores with streaming
// cache hints (data is touched exactly once).
template<int ROWS_PER_BLOCK>
__global__ __launch_bounds__(256, 8)
void butterfly_apply(const float4* __restrict__ x4, float4* __restrict__ o4,
                     int batch) {
    const int c = blockIdx.x * blockDim.x + threadIdx.x;   // 0..N4-1
    const float4 M0 = __ldg(&g_comp[2 * c + 0]);
    const float4 M1 = __ldg(&g_comp[2 * c + 1]);

    const int row0 = blockIdx.y * ROWS_PER_BLOCK;
    const int rmax = min(ROWS_PER_BLOCK, batch - row0);
    size_t idx = (size_t)row0 * N4 + c;
#pragma unroll 4
    for (int r = 0; r < rmax; ++r, idx += N4) {
        const float4 v = __ldcs(&x4[idx]);
        float4 y;
        y.x = fmaf(v.y, M0.z, v.x * M0.x);
        y.y = fmaf(v.y, M0.w, v.x * M0.y);
        y.z = fmaf(v.w, M1.z, v.z * M1.x);
        y.w = fmaf(v.w, M1.w, v.z * M1.y);
        __stcs(&o4[idx], y);
    }
}

extern "C" void kernel_launch(void* const* d_in, const int* in_sizes, int n_in,
                              void* d_out, int out_size) {
    const float* x = (const float*)d_in[0];   // [batch, SIZE] fp32
    const float* W = (const float*)d_in[1];   // [LOG_N, NPAIRS, 2, 2] fp32
    float* out = (float*)d_out;               // [batch, SIZE] fp32

    const int batch = in_sizes[0] / SIZE;

    // 1) compose per-pair 2x2 chains (tiny: 2048 threads)
    butterfly_compose<<<(NPAIRS + 255) / 256, 256>>>(W);

    // 2) one streaming pass over x
    constexpr int RPB = 16;                    // rows per block
    dim3 grid(N4 / 256, (batch + RPB - 1) / RPB);
    butterfly_apply<RPB><<<grid, 256>>>((const float4*)x, (float4*)out, batch);
}